// round 14
// baseline (speedup 1.0000x reference)
#include <cuda_runtime.h>
#include <cstdint>

#define EXPERTS 16
#define CIN     16
#define COUT    64
#define HW      16384            // 128*128
#define NPIX    131072
#define LOGIT_OFF 8388608
#define NPAIR   256              // lo*16+hi (120 valid)
#define PCHUNK  128              // pixels per expert block
#define MAXBLK  1280             // >= 131072/128 + 119 = 1143

// ---------------- scratch (device globals; ~4.6 MB total, exact-sized) ----------
__device__ int   g_cnt2[NPAIR];              // per-pair counts
__device__ int   g_off [NPAIR];              // exclusive-scan bases
__device__ int   g_fill[NPAIR];              // placement cursors
__device__ int2  g_pw  [NPIX];               // per-pixel (pid, wlo bits)   1 MB
__device__ int   g_pix [NPIX];               // compact pixel ids         0.5 MB
__device__ float g_gw  [NPIX];               // compact wlo               0.5 MB
__device__ float g_wT  [EXPERTS * 144 * 64]; // [e][ci*9+k][cout]        0.59 MB
__device__ int   g_sched[2048];
__device__ int   g_total;

// ---------------- f32x2 helpers ----------------
__device__ __forceinline__ unsigned long long pack2(float lo, float hi) {
    unsigned long long r;
    asm("mov.b64 %0, {%1, %2};" : "=l"(r) : "f"(lo), "f"(hi));
    return r;
}
__device__ __forceinline__ void fma2(unsigned long long& d, unsigned long long a, unsigned long long b) {
    asm("fma.rn.f32x2 %0, %1, %2, %0;" : "+l"(d) : "l"(a), "l"(b));
}
__device__ __forceinline__ float lo2(unsigned long long v) { return __uint_as_float((unsigned)(v & 0xFFFFFFFFull)); }
__device__ __forceinline__ float hi2(unsigned long long v) { return __uint_as_float((unsigned)(v >> 32)); }

// ---------------- kernel 0: reset ----------------
__global__ void reset_kernel() { g_cnt2[threadIdx.x] = 0; }

// ---------------- kernel 1: weight pre-transpose (once, coalesced writes) ------
__global__ void transpose_w_kernel(const float* __restrict__ ew) {
    int e = blockIdx.x;
    for (int i = threadIdx.x; i < 144 * 64; i += 256) {
        int cout = i & 63;
        int cik  = i >> 6;
        g_wT[e * 9216 + i] = ew[e * 9216 + cout * 144 + cik];
    }
}

// ---------------- kernel 2: gate (logits, top-2, pair id + weight, counts) -----
__global__ void gate_kernel(const float* __restrict__ x,
                            const float* __restrict__ gw,
                            const float* __restrict__ gb,
                            float* __restrict__ out_logits) {
    __shared__ float sgw[256];
    __shared__ float sgb[16];
    __shared__ int   scnt[256];
    int tid = threadIdx.x;
    sgw[tid] = gw[tid];
    scnt[tid] = 0;
    if (tid < 16) sgb[tid] = gb[tid];
    __syncthreads();

    int p  = blockIdx.x * 256 + tid;
    int b  = p >> 14;
    int hw = p & (HW - 1);

    float xv[CIN];
#pragma unroll
    for (int c = 0; c < CIN; c++) xv[c] = x[(b * CIN + c) * HW + hw];

    float best = -1e30f, second = -1e30f;
    int bi = 0, si = 0;
#pragma unroll
    for (int o = 0; o < 16; o++) {
        float l = sgb[o];
#pragma unroll
        for (int c = 0; c < CIN; c++) l = fmaf(sgw[o * 16 + c], xv[c], l);
        out_logits[(b * 16 + o) * HW + hw] = l;
        if (l > best) { second = best; si = bi; best = l; bi = o; }
        else if (l > second) { second = l; si = o; }
    }
    // softmax + top-2 renorm collapses exactly: w_best = 1/(1+exp(l2-l1))
    float w0 = 1.0f / (1.0f + expf(second - best));

    int lo = min(bi, si), hi = max(bi, si);
    int pid = lo * 16 + hi;
    float wlo = (bi < si) ? w0 : (1.0f - w0);

    g_pw[p] = make_int2(pid, __float_as_int(wlo));

    atomicAdd(&scnt[pid], 1);
    __syncthreads();
    if (scnt[tid]) atomicAdd(&g_cnt2[tid], scnt[tid]);
}

// ---------------- kernel 3: scan + schedule (1 block, 256 threads) -------------
__global__ void scan_sched_kernel() {
    __shared__ int a[256];
    int tid = threadIdx.x;
    int c  = g_cnt2[tid];
    int ch = (c + PCHUNK - 1) / PCHUNK;
    a[tid] = c;
    __syncthreads();
    // inclusive scan of counts
    for (int off = 1; off < 256; off <<= 1) {
        int v = a[tid];
        if (tid >= off) v += a[tid - off];
        __syncthreads();
        a[tid] = v;
        __syncthreads();
    }
    int off_excl = a[tid] - c;        // exclusive base into compact arrays
    g_off [tid] = off_excl;
    g_fill[tid] = off_excl;
    __syncthreads();

    // chunk-count scan for the schedule
    a[tid] = ch;
    __syncthreads();
    for (int off = 1; off < 256; off <<= 1) {
        int v = a[tid];
        if (tid >= off) v += a[tid - off];
        __syncthreads();
        a[tid] = v;
        __syncthreads();
    }
    int cbase = a[tid] - ch;
    for (int j = 0; j < ch; j++) {
        int slot = cbase + j;
        if (slot < 2048) g_sched[slot] = (tid << 16) | j;
    }
    if (tid == 255) g_total = min(a[255], MAXBLK);
}

// ---------------- kernel 4: placement into compact bins (block-aggregated) -----
__global__ void place_kernel() {
    __shared__ int scnt[256];
    __shared__ int sbase[256];
    int tid = threadIdx.x;
    scnt[tid] = 0;
    __syncthreads();

    int p = blockIdx.x * 256 + tid;
    int2 pw = g_pw[p];
    int pid = pw.x;
    int r = atomicAdd(&scnt[pid], 1);
    __syncthreads();
    sbase[tid] = scnt[tid] ? atomicAdd(&g_fill[tid], scnt[tid]) : 0;
    __syncthreads();

    int q = sbase[pid] + r;          // always < NPIX: total entries == NPIX exactly
    g_pix[q] = p;
    g_gw [q] = __int_as_float(pw.y);
}

// ---------------- kernel 5: pair conv ----------------
// 256 thr = 8 warps (cg = 8-cout group). Thread: 4 pixels x 8 couts x 2 experts.
// Block: 128 pixels, 64 couts, both experts of one pair. Plain STG epilogue.
__global__ void __launch_bounds__(256, 2)
expert_kernel(const float* __restrict__ x,
              const float* __restrict__ eb,
              float* __restrict__ out) {
    extern __shared__ float smem[];
    float* wsm = smem;                  // 2 * 9216  [expert][cik][cout]
    float* bsm = smem + 18432;          // 128
    float* As  = smem + 18560;          // 2 * 9 * 128 double-buffered x-stage

    int bid = blockIdx.x;
    if (bid >= g_total) return;
    int s     = g_sched[bid];
    int pair  = s >> 16;
    int chunk = s & 0xFFFF;
    int elo = pair >> 4, ehi = pair & 15;
    int n     = g_cnt2[pair];
    int start = g_off[pair];
    int base  = chunk * PCHUNK;

    int tid  = threadIdx.x;
    int lane = tid & 31;
    int cg   = tid >> 5;

    // coalesced weight loads from pre-transposed layout
    {
        const float* wlo_g = g_wT + elo * 9216;
        const float* whi_g = g_wT + ehi * 9216;
#pragma unroll 4
        for (int i = tid; i < 9216; i += 256) wsm[i] = wlo_g[i];
#pragma unroll 4
        for (int i = tid; i < 9216; i += 256) wsm[9216 + i] = whi_g[i];
    }
    if (tid < 64)       bsm[tid] = eb[elo * 64 + tid];
    else if (tid < 128) bsm[tid] = eb[ehi * 64 + (tid - 64)];

    // staging assignment: pix = tid&127; tp 0 -> taps 0..3, tp 1 -> taps 4..8
    int pix = tid & 127;
    int tp  = tid >> 7;
    bool sv = (base + pix) < n;
    int sp  = sv ? g_pix[start + base + pix] : 0;
    int sb  = sp >> 14, shw = sp & (HW - 1);
    int sh  = shw >> 7, sw = shw & 127;
    const float* xb = x + sb * (CIN * HW) + shw;
    bool hm = sh > 0, hp = sh < 127, wm = sw > 0, wp = sw < 127;

#define TAPS_LO(tv, xc)                                        \
    do {                                                       \
        tv[0] = (sv && hm && wm) ? (xc)[-129] : 0.f;           \
        tv[1] = (sv && hm)       ? (xc)[-128] : 0.f;           \
        tv[2] = (sv && hm && wp) ? (xc)[-127] : 0.f;           \
        tv[3] = (sv && wm)       ? (xc)[-1]   : 0.f;           \
    } while (0)
#define TAPS_HI(tv, xc)                                        \
    do {                                                       \
        tv[4] =  sv              ? (xc)[0]    : 0.f;           \
        tv[5] = (sv && wp)       ? (xc)[1]    : 0.f;           \
        tv[6] = (sv && hp && wm) ? (xc)[127]  : 0.f;           \
        tv[7] = (sv && hp)       ? (xc)[128]  : 0.f;           \
        tv[8] = (sv && hp && wp) ? (xc)[129]  : 0.f;           \
    } while (0)

    // stage ci = 0 into buffer 0
    {
        float t[9];
        if (tp == 0) {
            TAPS_LO(t, xb);
#pragma unroll
            for (int k = 0; k < 4; k++) As[k * 128 + pix] = t[k];
        } else {
            TAPS_HI(t, xb);
#pragma unroll
            for (int k = 4; k < 9; k++) As[k * 128 + pix] = t[k];
        }
    }
    __syncthreads();   // weights + bias + stage(0) visible

    // accumulators: [expert][4 pixels][4 f32x2]
    unsigned long long accA[4][4], accB[4][4];
    {
        const float* bl = bsm + cg * 8;
        const float* bh = bsm + 64 + cg * 8;
#pragma unroll
        for (int j = 0; j < 4; j++) {
#pragma unroll
            for (int c = 0; c < 4; c++) {
                accA[j][c] = pack2(bl[2 * c], bl[2 * c + 1]);
                accB[j][c] = pack2(bh[2 * c], bh[2 * c + 1]);
            }
        }
    }

    int buf = 0;
#pragma unroll 1
    for (int ci = 0; ci < CIN; ci++) {
        // prefetch next ci's taps (LDG latency hidden under the FMA block)
        float t[9];
        if (ci < CIN - 1) {
            const float* xc = xb + (ci + 1) * HW;
            if (tp == 0) TAPS_LO(t, xc); else TAPS_HI(t, xc);
        }

        const float* Ab = As + buf * 1152;
        const float* wl = wsm + ci * 576 + cg * 8;
        const float* wh = wsm + 9216 + ci * 576 + cg * 8;
#pragma unroll
        for (int k = 0; k < 9; k++) {
            float xv[4];
            const float* Ak = Ab + k * 128 + lane;
#pragma unroll
            for (int j = 0; j < 4; j++) xv[j] = Ak[32 * j];
            float4 lA = *(const float4*)(wl + k * 64);
            float4 lB = *(const float4*)(wl + k * 64 + 4);
            float4 hA = *(const float4*)(wh + k * 64);
            float4 hB = *(const float4*)(wh + k * 64 + 4);
            unsigned long long l01 = pack2(lA.x, lA.y), l23 = pack2(lA.z, lA.w);
            unsigned long long l45 = pack2(lB.x, lB.y), l67 = pack2(lB.z, lB.w);
            unsigned long long h01 = pack2(hA.x, hA.y), h23 = pack2(hA.z, hA.w);
            unsigned long long h45 = pack2(hB.x, hB.y), h67 = pack2(hB.z, hB.w);
#pragma unroll
            for (int j = 0; j < 4; j++) {
                unsigned long long xx = pack2(xv[j], xv[j]);
                fma2(accA[j][0], xx, l01);
                fma2(accA[j][1], xx, l23);
                fma2(accA[j][2], xx, l45);
                fma2(accA[j][3], xx, l67);
                fma2(accB[j][0], xx, h01);
                fma2(accB[j][1], xx, h23);
                fma2(accB[j][2], xx, h45);
                fma2(accB[j][3], xx, h67);
            }
        }

        if (ci < CIN - 1) {
            float* An = As + (buf ^ 1) * 1152;
            if (tp == 0) {
#pragma unroll
                for (int k = 0; k < 4; k++) An[k * 128 + pix] = t[k];
            } else {
#pragma unroll
                for (int k = 4; k < 9; k++) An[k * 128 + pix] = t[k];
            }
            __syncthreads();   // stage(ci+1) written AND stage(ci) reads done
            buf ^= 1;
        }
    }
#undef TAPS_LO
#undef TAPS_HI

    // epilogue: single plain store per output element (no atomics, no pre-zero)
#pragma unroll 1
    for (int j = 0; j < 4; j++) {
        int idx = base + lane + 32 * j;
        if (idx >= n) continue;
        int   p   = g_pix[start + idx];
        float wl  = g_gw [start + idx];
        float whv = 1.0f - wl;
        int pb  = p >> 14;
        int phw = p & (HW - 1);
        float* ob = out + (pb * COUT + cg * 8) * HW + phw;
#pragma unroll
        for (int c = 0; c < 4; c++) {
            ob[(2 * c)     * HW] = wl * lo2(accA[j][c]) + whv * lo2(accB[j][c]);
            ob[(2 * c + 1) * HW] = wl * hi2(accA[j][c]) + whv * hi2(accB[j][c]);
        }
    }
}

// ---------------- launch ----------------
extern "C" void kernel_launch(void* const* d_in, const int* in_sizes, int n_in,
                              void* d_out, int out_size) {
    const float* x  = (const float*)d_in[0];   // (8,16,128,128)
    const float* gw = (const float*)d_in[1];   // (16,16,1,1)
    const float* gb = (const float*)d_in[2];   // (16,)
    const float* ew = (const float*)d_in[3];   // (16,64,16,3,3)
    const float* eb = (const float*)d_in[4];   // (16,64)
    float* out    = (float*)d_out;
    float* logits = out + LOGIT_OFF;

    const int smem_bytes = (18432 + 128 + 2304) * 4;   // 83,456 B
    cudaFuncSetAttribute(expert_kernel,
                         cudaFuncAttributeMaxDynamicSharedMemorySize, smem_bytes);

    reset_kernel<<<1, 256>>>();
    transpose_w_kernel<<<EXPERTS, 256>>>(ew);
    gate_kernel<<<512, 256>>>(x, gw, gb, logits);
    scan_sched_kernel<<<1, 256>>>();
    place_kernel<<<512, 256>>>();
    expert_kernel<<<MAXBLK, 256, smem_bytes>>>(x, eb, out);
    (void)in_sizes; (void)n_in; (void)out_size;
}

// round 15
// speedup vs baseline: 1.0367x; 1.0367x over previous
#include <cuda_runtime.h>
#include <cstdint>

#define EXPERTS 16
#define CIN     16
#define COUT    64
#define HW      16384            // 128*128
#define NPIX    131072
#define LOGIT_OFF 8388608
#define NPAIR   256              // lo*16+hi (120 valid)
#define PCHUNK  128              // entries per conv block
#define MAXBLK  1280             // >= 131072/128 + 119 = 1143

// ---------------- scratch (device globals; ~4.6 MB, exact-sized) ----------------
__device__ int   g_cnt2[NPAIR];
__device__ int   g_off [NPAIR];
__device__ int   g_fill[NPAIR];
__device__ int2  g_pw  [NPIX];               // per-pixel (pid, wlo bits)
__device__ int   g_pix [NPIX];               // compact pixel ids
__device__ float g_gw  [NPIX];               // compact wlo
__device__ float g_wT  [EXPERTS * 144 * 64]; // [e][ci*9+k][cout]
__device__ int   g_sched[2048];
__device__ int   g_total;

// ---------------- f32x2 helpers ----------------
__device__ __forceinline__ unsigned long long pack2(float lo, float hi) {
    unsigned long long r;
    asm("mov.b64 %0, {%1, %2};" : "=l"(r) : "f"(lo), "f"(hi));
    return r;
}
__device__ __forceinline__ void fma2(unsigned long long& d, unsigned long long a, unsigned long long b) {
    asm("fma.rn.f32x2 %0, %1, %2, %0;" : "+l"(d) : "l"(a), "l"(b));
}
__device__ __forceinline__ float lo2(unsigned long long v) { return __uint_as_float((unsigned)(v & 0xFFFFFFFFull)); }
__device__ __forceinline__ float hi2(unsigned long long v) { return __uint_as_float((unsigned)(v >> 32)); }

// ---------------- kernel 1: prep = weight transpose (blocks 0-15) + reset (16) --
__global__ void prep_kernel(const float* __restrict__ ew) {
    int e = blockIdx.x;
    if (e < EXPERTS) {
        for (int i = threadIdx.x; i < 144 * 64; i += 256) {
            int cout = i & 63;
            int cik  = i >> 6;
            g_wT[e * 9216 + i] = ew[e * 9216 + cout * 144 + cik];
        }
    } else {
        g_cnt2[threadIdx.x] = 0;
    }
}

// ---------------- kernel 2: gate (logits, top-2, pair id + weight, counts) -----
__global__ void gate_kernel(const float* __restrict__ x,
                            const float* __restrict__ gw,
                            const float* __restrict__ gb,
                            float* __restrict__ out_logits) {
    __shared__ float sgw[256];
    __shared__ float sgb[16];
    __shared__ int   scnt[256];
    int tid = threadIdx.x;
    sgw[tid] = gw[tid];
    scnt[tid] = 0;
    if (tid < 16) sgb[tid] = gb[tid];
    __syncthreads();

    int p  = blockIdx.x * 256 + tid;
    int b  = p >> 14;
    int hw = p & (HW - 1);

    float xv[CIN];
#pragma unroll
    for (int c = 0; c < CIN; c++) xv[c] = x[(b * CIN + c) * HW + hw];

    float best = -1e30f, second = -1e30f;
    int bi = 0, si = 0;
#pragma unroll
    for (int o = 0; o < 16; o++) {
        float l = sgb[o];
#pragma unroll
        for (int c = 0; c < CIN; c++) l = fmaf(sgw[o * 16 + c], xv[c], l);
        out_logits[(b * 16 + o) * HW + hw] = l;
        if (l > best) { second = best; si = bi; best = l; bi = o; }
        else if (l > second) { second = l; si = o; }
    }
    // softmax + top-2 renorm collapses exactly: w_best = 1/(1+exp(l2-l1))
    float w0 = 1.0f / (1.0f + expf(second - best));

    int lo = min(bi, si), hi = max(bi, si);
    int pid = lo * 16 + hi;
    float wlo = (bi < si) ? w0 : (1.0f - w0);

    g_pw[p] = make_int2(pid, __float_as_int(wlo));

    atomicAdd(&scnt[pid], 1);
    __syncthreads();
    if (scnt[tid]) atomicAdd(&g_cnt2[tid], scnt[tid]);
}

// ---------------- kernel 3: scan + schedule (1 block, 256 threads) -------------
__global__ void scan_sched_kernel() {
    __shared__ int a[256];
    int tid = threadIdx.x;
    int c  = g_cnt2[tid];
    int ch = (c + PCHUNK - 1) / PCHUNK;
    a[tid] = c;
    __syncthreads();
    for (int off = 1; off < 256; off <<= 1) {
        int v = a[tid];
        if (tid >= off) v += a[tid - off];
        __syncthreads();
        a[tid] = v;
        __syncthreads();
    }
    int off_excl = a[tid] - c;
    g_off [tid] = off_excl;
    g_fill[tid] = off_excl;
    __syncthreads();

    a[tid] = ch;
    __syncthreads();
    for (int off = 1; off < 256; off <<= 1) {
        int v = a[tid];
        if (tid >= off) v += a[tid - off];
        __syncthreads();
        a[tid] = v;
        __syncthreads();
    }
    int cbase = a[tid] - ch;
    for (int j = 0; j < ch; j++) {
        int slot = cbase + j;
        if (slot < 2048) g_sched[slot] = (tid << 16) | j;
    }
    if (tid == 255) g_total = min(a[255], MAXBLK);
}

// ---------------- kernel 4: placement into compact bins --------------------------
__global__ void place_kernel() {
    __shared__ int scnt[256];
    __shared__ int sbase[256];
    int tid = threadIdx.x;
    scnt[tid] = 0;
    __syncthreads();

    int p = blockIdx.x * 256 + tid;
    int2 pw = g_pw[p];
    int pid = pw.x;
    int r = atomicAdd(&scnt[pid], 1);
    __syncthreads();
    sbase[tid] = scnt[tid] ? atomicAdd(&g_fill[tid], scnt[tid]) : 0;
    __syncthreads();

    int q = sbase[pid] + r;          // total entries == NPIX exactly, never overflows
    g_pix[q] = p;
    g_gw [q] = __int_as_float(pw.y);
}

// ---------------- kernel 5: pair conv — R4 core, one expert per thread-half ------
// 256 thr: ent = tid&127 (entry slot), tg = tid>>7 (0 = expert-lo, 1 = expert-hi).
// Thread = 1 entry x 64 couts x 1 expert (32 u64 accs); taps direct to registers,
// no mainloop syncs. Combine via padded smem exchange, single plain STG per elem.
__global__ void __launch_bounds__(256, 2)
pair_conv_kernel(const float* __restrict__ x,
                 const float* __restrict__ eb,
                 float* __restrict__ out) {
    extern __shared__ float smem[];
    float* wsm  = smem;                  // 2 * 9216   [tg][cik][cout]
    float* bsm  = smem + 18432;          // 128
    float* exch = smem + 18560;          // 128 * 65 (stride-65: conflict-free)

    int bid = blockIdx.x;
    if (bid >= g_total) return;
    int s     = g_sched[bid];
    int pair  = s >> 16;
    int chunk = s & 0xFFFF;
    int elo = pair >> 4, ehi = pair & 15;
    int n     = g_cnt2[pair];
    int start = g_off[pair];
    int base  = chunk * PCHUNK;

    int tid = threadIdx.x;
    int ent = tid & 127;
    int tg  = tid >> 7;
    int myexp = tg ? ehi : elo;

    // each 128-thread half loads its expert's weights (coalesced from g_wT)
    {
        const float* wg = g_wT + myexp * 9216;
        float* wd = wsm + tg * 9216;
        for (int i = ent; i < 9216; i += 128) wd[i] = wg[i];
    }
    if (ent < 64) bsm[tg * 64 + ent] = eb[myexp * 64 + ent];

    // entry decode
    int gi = start + base + ent;
    bool v = (base + ent) < n;
    int p  = v ? g_pix[gi] : 0;
    int pb  = p >> 14;
    int phw = p & (HW - 1);
    int ph  = phw >> 7, pw = phw & 127;
    const float* xb = x + pb * (CIN * HW) + phw;
    bool hm = ph > 0, hp = ph < 127, wm = pw > 0, wp = pw < 127;

    __syncthreads();   // weights + bias visible

    // accumulators: 64 couts as 32 f32x2, init with bias
    unsigned long long acc[32];
    {
        const float* bb = bsm + tg * 64;
#pragma unroll
        for (int c = 0; c < 32; c++) acc[c] = pack2(bb[2 * c], bb[2 * c + 1]);
    }

    const float* wd = wsm + tg * 9216;
#pragma unroll 1
    for (int ci = 0; ci < CIN; ci++) {
        const float* xc = xb + ci * HW;
        float t[9];
        t[0] = (v && hm && wm) ? xc[-129] : 0.f;
        t[1] = (v && hm)       ? xc[-128] : 0.f;
        t[2] = (v && hm && wp) ? xc[-127] : 0.f;
        t[3] = (v && wm)       ? xc[-1]   : 0.f;
        t[4] =  v              ? xc[0]    : 0.f;
        t[5] = (v && wp)       ? xc[1]    : 0.f;
        t[6] = (v && hp && wm) ? xc[127]  : 0.f;
        t[7] = (v && hp)       ? xc[128]  : 0.f;
        t[8] = (v && hp && wp) ? xc[129]  : 0.f;
#pragma unroll
        for (int k = 0; k < 9; k++) {
            unsigned long long xx = pack2(t[k], t[k]);
            const ulonglong2* wr = (const ulonglong2*)(wd + (ci * 9 + k) * 64);
#pragma unroll
            for (int c = 0; c < 16; c++) {
                ulonglong2 wv = wr[c];           // broadcast LDS.128
                fma2(acc[2 * c],     xx, wv.x);
                fma2(acc[2 * c + 1], xx, wv.y);
            }
        }
    }

    // combine: tg1 deposits weighted partial, tg0 adds and stores (plain STG)
    float gwv = v ? g_gw[gi] : 0.0f;
    float wf  = tg ? (1.0f - gwv) : gwv;

    if (tg == 1) {
        float* ex = exch + ent * 65;
#pragma unroll
        for (int c = 0; c < 32; c++) {
            ex[2 * c]     = wf * lo2(acc[c]);
            ex[2 * c + 1] = wf * hi2(acc[c]);
        }
    }
    __syncthreads();
    if (tg == 0 && v) {
        const float* ex = exch + ent * 65;
        float* ob = out + (pb * COUT) * HW + phw;
#pragma unroll
        for (int c = 0; c < 32; c++) {
            ob[(2 * c)     * HW] = wf * lo2(acc[c]) + ex[2 * c];
            ob[(2 * c + 1) * HW] = wf * hi2(acc[c]) + ex[2 * c + 1];
        }
    }
}

// ---------------- launch ----------------
extern "C" void kernel_launch(void* const* d_in, const int* in_sizes, int n_in,
                              void* d_out, int out_size) {
    const float* x  = (const float*)d_in[0];   // (8,16,128,128)
    const float* gw = (const float*)d_in[1];   // (16,16,1,1)
    const float* gb = (const float*)d_in[2];   // (16,)
    const float* ew = (const float*)d_in[3];   // (16,64,16,3,3)
    const float* eb = (const float*)d_in[4];   // (16,64)
    float* out    = (float*)d_out;
    float* logits = out + LOGIT_OFF;

    const int smem_bytes = (18432 + 128 + 128 * 65) * 4;   // 107,520 B
    cudaFuncSetAttribute(pair_conv_kernel,
                         cudaFuncAttributeMaxDynamicSharedMemorySize, smem_bytes);

    prep_kernel<<<EXPERTS + 1, 256>>>(ew);
    gate_kernel<<<512, 256>>>(x, gw, gb, logits);
    scan_sched_kernel<<<1, 256>>>();
    place_kernel<<<512, 256>>>();
    pair_conv_kernel<<<MAXBLK, 256, smem_bytes>>>(x, eb, out);
    (void)in_sizes; (void)n_in; (void)out_size;
}

// round 16
// speedup vs baseline: 1.8001x; 1.7364x over previous
#include <cuda_runtime.h>
#include <cstdint>

#define EXPERTS 16
#define CIN     16
#define COUT    64
#define HW      16384            // 128*128
#define NPIX    131072
#define LOGIT_OFF 8388608
#define NPAIR   256              // lo*16+hi (120 valid)
#define PCHUNK  128              // entries per conv block (2 passes x 64)
#define EPP     64               // entries per pass
#define MAXBLK  1280             // >= 131072/128 + 119 = 1143

// ---------------- scratch (device globals; ~4.6 MB, exact-sized) ----------------
__device__ int   g_cnt2[NPAIR];
__device__ int   g_off [NPAIR];
__device__ int   g_fill[NPAIR];
__device__ int2  g_pw  [NPIX];               // per-pixel (pid, wlo bits)
__device__ int   g_pix [NPIX];               // compact pixel ids
__device__ float g_gw  [NPIX];               // compact wlo
__device__ float g_wT  [EXPERTS * 144 * 64]; // [e][ci*9+k][cout]
__device__ int   g_sched[2048];
__device__ int   g_total;

// ---------------- f32x2 helpers ----------------
__device__ __forceinline__ unsigned long long pack2(float lo, float hi) {
    unsigned long long r;
    asm("mov.b64 %0, {%1, %2};" : "=l"(r) : "f"(lo), "f"(hi));
    return r;
}
__device__ __forceinline__ void fma2(unsigned long long& d, unsigned long long a, unsigned long long b) {
    asm("fma.rn.f32x2 %0, %1, %2, %0;" : "+l"(d) : "l"(a), "l"(b));
}
__device__ __forceinline__ float lo2(unsigned long long v) { return __uint_as_float((unsigned)(v & 0xFFFFFFFFull)); }
__device__ __forceinline__ float hi2(unsigned long long v) { return __uint_as_float((unsigned)(v >> 32)); }

// ---------------- kernel 1: prep = weight transpose (blocks 0-15) + reset (16) --
__global__ void prep_kernel(const float* __restrict__ ew) {
    int e = blockIdx.x;
    if (e < EXPERTS) {
        for (int i = threadIdx.x; i < 144 * 64; i += 256) {
            int cout = i & 63;
            int cik  = i >> 6;
            g_wT[e * 9216 + i] = ew[e * 9216 + cout * 144 + cik];
        }
    } else {
        g_cnt2[threadIdx.x] = 0;
    }
}

// ---------------- kernel 2: gate (logits, top-2, pair id + weight, counts) -----
__global__ void gate_kernel(const float* __restrict__ x,
                            const float* __restrict__ gw,
                            const float* __restrict__ gb,
                            float* __restrict__ out_logits) {
    __shared__ float sgw[256];
    __shared__ float sgb[16];
    __shared__ int   scnt[256];
    int tid = threadIdx.x;
    sgw[tid] = gw[tid];
    scnt[tid] = 0;
    if (tid < 16) sgb[tid] = gb[tid];
    __syncthreads();

    int p  = blockIdx.x * 256 + tid;
    int b  = p >> 14;
    int hw = p & (HW - 1);

    float xv[CIN];
#pragma unroll
    for (int c = 0; c < CIN; c++) xv[c] = x[(b * CIN + c) * HW + hw];

    float best = -1e30f, second = -1e30f;
    int bi = 0, si = 0;
#pragma unroll
    for (int o = 0; o < 16; o++) {
        float l = sgb[o];
#pragma unroll
        for (int c = 0; c < CIN; c++) l = fmaf(sgw[o * 16 + c], xv[c], l);
        out_logits[(b * 16 + o) * HW + hw] = l;
        if (l > best) { second = best; si = bi; best = l; bi = o; }
        else if (l > second) { second = l; si = o; }
    }
    // softmax + top-2 renorm collapses exactly: w_best = 1/(1+exp(l2-l1))
    float w0 = 1.0f / (1.0f + expf(second - best));

    int lo = min(bi, si), hi = max(bi, si);
    int pid = lo * 16 + hi;
    float wlo = (bi < si) ? w0 : (1.0f - w0);

    g_pw[p] = make_int2(pid, __float_as_int(wlo));

    atomicAdd(&scnt[pid], 1);
    __syncthreads();
    if (scnt[tid]) atomicAdd(&g_cnt2[tid], scnt[tid]);
}

// ---------------- kernel 3: scan + schedule (1 block, 256 threads) -------------
__global__ void scan_sched_kernel() {
    __shared__ int a[256];
    int tid = threadIdx.x;
    int c  = g_cnt2[tid];
    int ch = (c + PCHUNK - 1) / PCHUNK;
    a[tid] = c;
    __syncthreads();
    for (int off = 1; off < 256; off <<= 1) {
        int v = a[tid];
        if (tid >= off) v += a[tid - off];
        __syncthreads();
        a[tid] = v;
        __syncthreads();
    }
    int off_excl = a[tid] - c;
    g_off [tid] = off_excl;
    g_fill[tid] = off_excl;
    __syncthreads();

    a[tid] = ch;
    __syncthreads();
    for (int off = 1; off < 256; off <<= 1) {
        int v = a[tid];
        if (tid >= off) v += a[tid - off];
        __syncthreads();
        a[tid] = v;
        __syncthreads();
    }
    int cbase = a[tid] - ch;
    for (int j = 0; j < ch; j++) {
        int slot = cbase + j;
        if (slot < 2048) g_sched[slot] = (tid << 16) | j;
    }
    if (tid == 255) g_total = min(a[255], MAXBLK);
}

// ---------------- kernel 4: placement into compact bins --------------------------
__global__ void place_kernel() {
    __shared__ int scnt[256];
    __shared__ int sbase[256];
    int tid = threadIdx.x;
    scnt[tid] = 0;
    __syncthreads();

    int p = blockIdx.x * 256 + tid;
    int2 pw = g_pw[p];
    int pid = pw.x;
    int r = atomicAdd(&scnt[pid], 1);
    __syncthreads();
    sbase[tid] = scnt[tid] ? atomicAdd(&g_fill[tid], scnt[tid]) : 0;
    __syncthreads();

    int q = sbase[pid] + r;          // total entries == NPIX exactly
    g_pix[q] = p;
    g_gw [q] = __int_as_float(pw.y);
}

// ---------------- kernel 5: pair conv, lane=cout / f32x2=entry-pair --------------
// 8 warps: tg = w>>2 (expert lo/hi), eg = w&3 (entry group of 16).
// Lane owns couts {lane, lane+32}; acc[j] = f32x2 over entries (2j, 2j+1).
// 2 passes x 64 entries per block. Plain STG epilogue via smem exchange.
// Smem (floats): wsm 18432 | bsm 128 | As 1152 | epix 128 | egw 128 | exch 4224
__global__ void __launch_bounds__(256, 2)
pair_conv_kernel(const float* __restrict__ x,
                 const float* __restrict__ eb,
                 float* __restrict__ out) {
    extern __shared__ float smem[];
    float* wsm  = smem;                   // [tg][cik][cout]
    float* bsm  = smem + 18432;
    float* As   = smem + 18560;           // 2 x 9 x 64 double-buffered x-stage
    int*   epix = (int*)(smem + 19712);   // 128 pixel ids (-1 = invalid)
    float* egw  = smem + 19840;           // 128 lo-expert weights
    float* exch = smem + 19968;           // 64 x 66 exchange

    int bid = blockIdx.x;
    if (bid >= g_total) return;
    int s     = g_sched[bid];
    int pair  = s >> 16;
    int chunk = s & 0xFFFF;
    int elo = pair >> 4, ehi = pair & 15;
    int n     = g_cnt2[pair];
    int start = g_off[pair];
    int base  = chunk * PCHUNK;

    int tid  = threadIdx.x;
    int lane = tid & 31;
    int w    = tid >> 5;
    int tg   = w >> 2;                    // 0 = expert-lo, 1 = expert-hi
    int eg   = w & 3;                     // entry group (16 entries)

    // coalesced weight + bias + entry-meta loads
    {
        const float* wlo_g = g_wT + elo * 9216;
        const float* whi_g = g_wT + ehi * 9216;
#pragma unroll 4
        for (int i = tid; i < 9216; i += 256) wsm[i] = wlo_g[i];
#pragma unroll 4
        for (int i = tid; i < 9216; i += 256) wsm[9216 + i] = whi_g[i];
    }
    if (tid < 64)       bsm[tid] = eb[elo * 64 + tid];
    else if (tid < 128) bsm[tid] = eb[ehi * 64 + (tid - 64)];
    if (tid < 128) {
        int ii = base + tid;
        bool okv = ii < n;
        epix[tid] = okv ? g_pix[start + ii] : -1;
        egw [tid] = okv ? g_gw [start + ii] : 0.0f;
    }
    __syncthreads();

    // staging identity: se = entry slot (0..63), sg = tap group
    int se = tid & 63;
    int sg = tid >> 6;                    // 0:{k0,k1} 1:{k2,k3} 2:{k4,k5} 3:{k6,k7,k8}

    float blane = bsm[tg * 64 + lane];
    float bl32  = bsm[tg * 64 + 32 + lane];
    const float* wd = wsm + tg * 9216;

#pragma unroll 1
    for (int pass = 0; pass < 2; pass++) {
        // ---- per-pass staging entry decode ----
        int sp = epix[pass * 64 + se];
        bool svalid = sp >= 0;
        int pbs  = sp >> 14;
        int phws = sp & (HW - 1);
        int phs  = phws >> 7, pws = phws & 127;
        const float* xb = x + pbs * (CIN * HW) + phws;
        bool hm = phs > 0, hp = phs < 127, wm = pws > 0, wp = pws < 127;

        // stage ci = 0 into buffer 0
        {
            const float* xc = xb;
            if (sg == 0) {
                As[0 * 64 + se] = (svalid && hm && wm) ? xc[-129] : 0.f;
                As[1 * 64 + se] = (svalid && hm)       ? xc[-128] : 0.f;
            } else if (sg == 1) {
                As[2 * 64 + se] = (svalid && hm && wp) ? xc[-127] : 0.f;
                As[3 * 64 + se] = (svalid && wm)       ? xc[-1]   : 0.f;
            } else if (sg == 2) {
                As[4 * 64 + se] =  svalid              ? xc[0]    : 0.f;
                As[5 * 64 + se] = (svalid && wp)       ? xc[1]    : 0.f;
            } else {
                As[6 * 64 + se] = (svalid && hp && wm) ? xc[127]  : 0.f;
                As[7 * 64 + se] = (svalid && hp)       ? xc[128]  : 0.f;
                As[8 * 64 + se] = (svalid && hp && wp) ? xc[129]  : 0.f;
            }
        }
        __syncthreads();

        // accumulators: 8 entry-pairs x 2 couts, init with bias
        unsigned long long accL[8], accH[8];
#pragma unroll
        for (int j = 0; j < 8; j++) {
            accL[j] = pack2(blane, blane);
            accH[j] = pack2(bl32,  bl32);
        }

        int buf = 0;
#pragma unroll 1
        for (int ci = 0; ci < CIN; ci++) {
            // prefetch next ci's taps (LDG hidden under the FMA block)
            float t0 = 0.f, t1 = 0.f, t2 = 0.f;
            if (ci < CIN - 1) {
                const float* xc = xb + (ci + 1) * HW;
                if (sg == 0) {
                    t0 = (svalid && hm && wm) ? xc[-129] : 0.f;
                    t1 = (svalid && hm)       ? xc[-128] : 0.f;
                } else if (sg == 1) {
                    t0 = (svalid && hm && wp) ? xc[-127] : 0.f;
                    t1 = (svalid && wm)       ? xc[-1]   : 0.f;
                } else if (sg == 2) {
                    t0 =  svalid              ? xc[0]    : 0.f;
                    t1 = (svalid && wp)       ? xc[1]    : 0.f;
                } else {
                    t0 = (svalid && hp && wm) ? xc[127]  : 0.f;
                    t1 = (svalid && hp)       ? xc[128]  : 0.f;
                    t2 = (svalid && hp && wp) ? xc[129]  : 0.f;
                }
            }

            const float* Ab   = As + buf * 576;
            const float* wrow = wd + ci * 576;
#pragma unroll
            for (int k = 0; k < 9; k++) {
                float wA = wrow[k * 64 + lane];          // per-lane distinct LDS.32
                float wB = wrow[k * 64 + 32 + lane];
                unsigned long long wa = pack2(wA, wA);
                unsigned long long wb = pack2(wB, wB);
                const ulonglong2* xq = (const ulonglong2*)(Ab + k * 64 + eg * 16);
                ulonglong2 q0 = xq[0], q1 = xq[1], q2 = xq[2], q3 = xq[3]; // broadcast LDS.128
                fma2(accL[0], q0.x, wa); fma2(accH[0], q0.x, wb);
                fma2(accL[1], q0.y, wa); fma2(accH[1], q0.y, wb);
                fma2(accL[2], q1.x, wa); fma2(accH[2], q1.x, wb);
                fma2(accL[3], q1.y, wa); fma2(accH[3], q1.y, wb);
                fma2(accL[4], q2.x, wa); fma2(accH[4], q2.x, wb);
                fma2(accL[5], q2.y, wa); fma2(accH[5], q2.y, wb);
                fma2(accL[6], q3.x, wa); fma2(accH[6], q3.x, wb);
                fma2(accL[7], q3.y, wa); fma2(accH[7], q3.y, wb);
            }

            if (ci < CIN - 1) {
                float* An = As + (buf ^ 1) * 576;
                if (sg == 0)      { An[0 * 64 + se] = t0; An[1 * 64 + se] = t1; }
                else if (sg == 1) { An[2 * 64 + se] = t0; An[3 * 64 + se] = t1; }
                else if (sg == 2) { An[4 * 64 + se] = t0; An[5 * 64 + se] = t1; }
                else              { An[6 * 64 + se] = t0; An[7 * 64 + se] = t1; An[8 * 64 + se] = t2; }
                __syncthreads();
                buf ^= 1;
            }
        }

        // ---- epilogue: tg1 deposits weighted partials, tg0 combines + stores ----
        if (tg == 1) {
#pragma unroll
            for (int j = 0; j < 8; j++) {
                int e0 = eg * 16 + 2 * j, e1 = e0 + 1;
                float wh0 = 1.0f - egw[pass * 64 + e0];
                float wh1 = 1.0f - egw[pass * 64 + e1];
                exch[e0 * 66 + lane]      = wh0 * lo2(accL[j]);
                exch[e1 * 66 + lane]      = wh1 * hi2(accL[j]);
                exch[e0 * 66 + 33 + lane] = wh0 * lo2(accH[j]);
                exch[e1 * 66 + 33 + lane] = wh1 * hi2(accH[j]);
            }
        }
        __syncthreads();
        if (tg == 0) {
#pragma unroll 1
            for (int j = 0; j < 8; j++) {
                int e0 = eg * 16 + 2 * j, e1 = e0 + 1;
                int sp0 = epix[pass * 64 + e0];
                if (sp0 >= 0) {
                    float wl = egw[pass * 64 + e0];
                    int pb = sp0 >> 14, phw = sp0 & (HW - 1);
                    float* ob = out + (pb * COUT) * HW + phw;
                    ob[lane * HW]        = wl * lo2(accL[j]) + exch[e0 * 66 + lane];
                    ob[(lane + 32) * HW] = wl * lo2(accH[j]) + exch[e0 * 66 + 33 + lane];
                }
                int sp1 = epix[pass * 64 + e1];
                if (sp1 >= 0) {
                    float wl = egw[pass * 64 + e1];
                    int pb = sp1 >> 14, phw = sp1 & (HW - 1);
                    float* ob = out + (pb * COUT) * HW + phw;
                    ob[lane * HW]        = wl * hi2(accL[j]) + exch[e1 * 66 + lane];
                    ob[(lane + 32) * HW] = wl * hi2(accH[j]) + exch[e1 * 66 + 33 + lane];
                }
            }
        }
        __syncthreads();   // exch reusable next pass
    }
}

// ---------------- launch ----------------
extern "C" void kernel_launch(void* const* d_in, const int* in_sizes, int n_in,
                              void* d_out, int out_size) {
    const float* x  = (const float*)d_in[0];   // (8,16,128,128)
    const float* gw = (const float*)d_in[1];   // (16,16,1,1)
    const float* gb = (const float*)d_in[2];   // (16,)
    const float* ew = (const float*)d_in[3];   // (16,64,16,3,3)
    const float* eb = (const float*)d_in[4];   // (16,64)
    float* out    = (float*)d_out;
    float* logits = out + LOGIT_OFF;

    const int smem_bytes = 24192 * 4;          // 96,768 B
    cudaFuncSetAttribute(pair_conv_kernel,
                         cudaFuncAttributeMaxDynamicSharedMemorySize, smem_bytes);

    prep_kernel<<<EXPERTS + 1, 256>>>(ew);
    gate_kernel<<<512, 256>>>(x, gw, gb, logits);
    scan_sched_kernel<<<1, 256>>>();
    place_kernel<<<512, 256>>>();
    pair_conv_kernel<<<MAXBLK, 256, smem_bytes>>>(x, eb, out);
    (void)in_sizes; (void)n_in; (void)out_size;
}